// round 4
// baseline (speedup 1.0000x reference)
#include <cuda_runtime.h>

#define HH 128
#define WW 128
#define BB 64
#define OO 32
#define KMAX 5
#define PITCH 136                 // PITCH mod 32 = 8; staging step 1-8k mod 32 is odd for all k
#define NROWS (HH + 2*KMAX + 1)   // logical u in [-KMAX, 128+KMAX], row = u + KMAX
#define TPB 256

__global__ __launch_bounds__(TPB) void dalayer_kernel(
    const float* __restrict__ X,
    const float* __restrict__ eps,
    const float* __restrict__ tmin,
    const float* __restrict__ tmax,
    float* __restrict__ out)
{
    extern __shared__ float simg[];   // [NROWS][PITCH], skewed layout

    const int tid = threadIdx.x;
    const int bx = blockIdx.x;
    const int o = bx & (OO - 1);      // consecutive CTAs share image b -> L2 reuse
    const int b = bx >> 5;

    // ---- affine params for this o (uniform per CTA; every thread computes same) ----
    float th[7];
    #pragma unroll
    for (int i = 0; i < 7; i++) {
        const float mn = tmin[i];
        th[i] = fmaf(tmax[i] - mn, eps[o * 7 + i], mn);
    }
    float s, c;
    sincosf(th[0], &s, &c);
    const float sx = th[1], sy = th[2], pX = th[3], pY = th[4], tx = th[5], ty = th[6];
    const float a00 = c * sx - s * pY;   // > 0 over this parameter range
    const float a01 = c * pX - s * sy;
    const float a10 = s * sx + c * pY;
    const float a11 = s * pX + c * sy;
    // px = a00*x + a01*y + offx  (pixel coords; 2/127 * 63.5 == 1 exactly)
    const float offx = 63.5f * (tx + 1.0f - a00 - a01);
    const float offy = 63.5f * (ty + 1.0f - a10 - a11);

    // skew factor: rotate sampling lines into smem rows
    int k = __float2int_rn(a10 / a00);
    k = min(max(k, -KMAX), KMAX);

    // ---- stage image b into skewed smem: simg[(y - k*x)&127 + KMAX][x] ----
    // lane = x (consecutive): smem addr step per lane = 1 - k*PITCH == odd mod 32 -> conflict-free
    const float* src = X + (size_t)b * (HH * WW);
    for (int j = tid; j < HH * WW; j += TPB) {
        const int x = j & (WW - 1);
        const int y = j >> 7;
        const float val = src[j];
        const int u = (y - k * x) & (HH - 1);
        simg[(u + KMAX) * PITCH + x] = val;
        if (u <= KMAX)                      // duplicate for logical u+128
            simg[(u + KMAX + HH) * PITCH + x] = val;
        if (u >= HH - KMAX)                 // duplicate for logical u-128
            simg[(u + KMAX - HH) * PITCH + x] = val;
    }

    __syncthreads();

    // thread owns fixed x; walks y in steps of 2
    const int x    = tid & (WW - 1);
    const int yini = tid >> 7;

    float px = fmaf(a01, (float)yini, fmaf(a00, (float)x, offx));
    float py = fmaf(a11, (float)yini, fmaf(a10, (float)x, offy));
    const float dpx = 2.0f * a01;
    const float dpy = 2.0f * a11;

    const int dkp = 1 - k * PITCH;    // element offset for the (x0+1) taps (uniform)

    float* __restrict__ outp = out + (size_t)(o * BB + b) * (HH * WW) + tid;

    #pragma unroll 8
    for (int it = 0; it < HH / 2; it++) {
        // clamp coordinates (not indices): x1=x0+1, y1=y0+1 always valid
        const float cx = fminf(fmaxf(px, 0.0f), 126.99999f);
        const float cy = fminf(fmaxf(py, 0.0f), 126.99999f);
        const int x0 = (int)cx;
        const int y0 = (int)cy;
        const float wx = cx - (float)x0;
        const float wy = cy - (float)y0;

        const int u0 = (y0 - k * x0) & (HH - 1);          // wrapped skew row
        const float* rr = simg + (u0 + KMAX) * PITCH + x0; // tap (x0, y0)
        const float* rc = rr + dkp;                        // tap (x0+1, y0)

        const float Ia = rr[0];
        const float Ib = rr[PITCH];       // (x0,   y0+1): logical u0+1
        const float Ic = rc[0];           // (x0+1, y0  ): logical u0-k
        const float Id = rc[PITCH];       // (x0+1, y0+1): logical u0-k+1

        const float t0 = fmaf(wx, Ic - Ia, Ia);
        const float t1 = fmaf(wx, Id - Ib, Ib);
        outp[it * TPB] = fmaf(wy, t1 - t0, t0);

        px += dpx;
        py += dpy;
    }
}

extern "C" void kernel_launch(void* const* d_in, const int* in_sizes, int n_in,
                              void* d_out, int out_size)
{
    const float* X    = (const float*)d_in[0];
    const float* eps  = (const float*)d_in[1];
    const float* tmin = (const float*)d_in[2];
    const float* tmax = (const float*)d_in[3];
    float* out = (float*)d_out;

    const int smem_bytes = NROWS * PITCH * sizeof(float);  // 139*136*4 = 75616
    static bool attr_set = false;
    if (!attr_set) {
        cudaFuncSetAttribute(dalayer_kernel,
                             cudaFuncAttributeMaxDynamicSharedMemorySize, smem_bytes);
        attr_set = true;
    }

    dalayer_kernel<<<BB * OO, TPB, smem_bytes>>>(X, eps, tmin, tmax, out);
}

// round 5
// speedup vs baseline: 2.6820x; 2.6820x over previous
#include <cuda_runtime.h>

#define HH 128
#define WW 128
#define BB 64
#define OO 32
#define NPIX (HH * WW)
#define OPITCH 66          // smem out-tile pitch over b (float2-aligned; 66 mod 32 = 2 -> 2-way on read only)
#define TPB 256

// 4 MB transposed copy of X: XT[src][b], b contiguous
__device__ float g_XT[NPIX * BB];

__global__ __launch_bounds__(256) void transpose_kernel(const float* __restrict__ X)
{
    __shared__ float t[32][33];
    const int s0 = blockIdx.x * 32;
    const int b0 = blockIdx.y * 32;
    const int tx = threadIdx.x & 31;
    const int ty = threadIdx.x >> 5;   // 0..7
    #pragma unroll
    for (int r = ty; r < 32; r += 8)
        t[tx][r] = X[(size_t)(b0 + r) * NPIX + s0 + tx];
    __syncthreads();
    #pragma unroll
    for (int r = ty; r < 32; r += 8)
        g_XT[(size_t)(s0 + r) * BB + b0 + tx] = t[r][tx];
}

__global__ __launch_bounds__(TPB) void dalayer_kernel(
    const float* __restrict__ eps,
    const float* __restrict__ tmin,
    const float* __restrict__ tmax,
    float* __restrict__ out)
{
    __shared__ float outs[WW][OPITCH];   // [x][b] result tile for one (o,y)

    const int tid  = threadIdx.x;
    const int lane = tid & 31;
    const int warp = tid >> 5;           // 0..7
    const int y = blockIdx.x;
    const int o = blockIdx.y;

    // ---- affine params for this o (uniform; every thread computes same) ----
    float th[7];
    #pragma unroll
    for (int i = 0; i < 7; i++) {
        const float mn = tmin[i];
        th[i] = fmaf(tmax[i] - mn, eps[o * 7 + i], mn);
    }
    float s, c;
    sincosf(th[0], &s, &c);
    const float sx = th[1], sy = th[2], pX = th[3], pY = th[4], tx = th[5], ty = th[6];
    const float a00 = c * sx - s * pY;
    const float a01 = c * pX - s * sy;
    const float a10 = s * sx + c * pY;
    const float a11 = s * pX + c * sy;
    // pixel coords: px = a00*x + a01*y + offx   [(2/127)*63.5 == 1 exactly]
    const float offx = 63.5f * (tx + 1.0f - a00 - a01);
    const float offy = 63.5f * (ty + 1.0f - a10 - a11);

    const float rowx = fmaf(a01, (float)y, offx);
    const float rowy = fmaf(a11, (float)y, offy);

    // ---- compute: warp w handles x = 16w..16w+15; lane = b-pair {2l, 2l+1} ----
    #pragma unroll 4
    for (int i = 0; i < 16; i++) {
        const int x = warp * 16 + i;

        const float cx = fminf(fmaxf(fmaf(a00, (float)x, rowx), 0.0f), 126.99999f);
        const float cy = fminf(fmaxf(fmaf(a10, (float)x, rowy), 0.0f), 126.99999f);
        const int x0 = (int)cx;
        const int y0 = (int)cy;
        const float wx = cx - (float)x0;
        const float wy = cy - (float)y0;

        // all lanes load the 4 tap lines (64 b each) -> fully coalesced, no conflicts
        const float2* p = reinterpret_cast<const float2*>(g_XT + (size_t)(y0 * WW + x0) * BB) + lane;
        const float2 Ia = p[0];
        const float2 Ic = p[32];               // (x0+1, y0):   +64 floats
        const float2 Ib = p[WW * 32];          // (x0,   y0+1): +8192 floats
        const float2 Id = p[WW * 32 + 32];

        float2 r;
        {
            const float t0 = fmaf(wx, Ic.x - Ia.x, Ia.x);
            const float t1 = fmaf(wx, Id.x - Ib.x, Ib.x);
            r.x = fmaf(wy, t1 - t0, t0);
        }
        {
            const float t0 = fmaf(wx, Ic.y - Ia.y, Ia.y);
            const float t1 = fmaf(wx, Id.y - Ib.y, Ib.y);
            r.y = fmaf(wy, t1 - t0, t0);
        }
        *reinterpret_cast<float2*>(&outs[x][2 * lane]) = r;   // contiguous 256B -> conflict-free
    }

    __syncthreads();

    // ---- writeout: warp w handles b = 8w..8w+7; coalesced STG ----
    #pragma unroll
    for (int b8 = 0; b8 < 8; b8++) {
        const int b = warp * 8 + b8;
        float* __restrict__ dst = out + (size_t)(o * BB + b) * NPIX + y * WW;
        #pragma unroll
        for (int j = 0; j < 4; j++) {
            const int x = j * 32 + lane;
            dst[x] = outs[x][b];               // LDS stride 66 -> 2-way, acceptable
        }
    }
}

extern "C" void kernel_launch(void* const* d_in, const int* in_sizes, int n_in,
                              void* d_out, int out_size)
{
    const float* X    = (const float*)d_in[0];
    const float* eps  = (const float*)d_in[1];
    const float* tmin = (const float*)d_in[2];
    const float* tmax = (const float*)d_in[3];
    float* out = (float*)d_out;

    dim3 tgrid(NPIX / 32, BB / 32);            // 512 x 2
    transpose_kernel<<<tgrid, 256>>>(X);

    dim3 grid(HH, OO);                         // 128 x 32 CTAs
    dalayer_kernel<<<grid, TPB>>>(eps, tmin, tmax, out);
}